// round 4
// baseline (speedup 1.0000x reference)
#include <cuda_runtime.h>
#include <cstdint>

#define DIMX 64
#define HIDX 128
#define BATCH 8192
#define NSTEPS 100
#define ROWS 64
#define NCTAS 128
#define NTHREADS 512
#define DT_C 0.01f
#define SQDT_C 0.1f

// ── smem float offsets (layout identical to R2) ─────────────────────
#define OFF_X   0        // x tf32 copy 64x64 (perm+swz); doubles as f-buffer
#define OFF_HD  4096     // h_drift 64x128 (perm+swz)
#define OFF_HG  12288    // h_diff  64x128
#define OFF_W1D 20480    // W1d^T: 128 rows x 64 (perm+swz)
#define OFF_W1G 28672
#define OFF_W2D 36864    // W2d^T: 64 rows x 128
#define OFF_W2G 45056
#define OFF_NZ  53248    // noise 64x64 (swz only, no perm)
#define OFF_B1D 57344
#define OFF_B1G 57472
#define OFF_B2D 57600
#define OFF_B2G 57664
#define SMEM_FLOATS 57728
#define SMEM_BYTES (SMEM_FLOATS * 4)

// position of element k inside its 8-block: pairs (k, k+4) stored adjacent
__device__ __forceinline__ int permpos(int k) {
    return ((k >> 3) << 3) + 2 * (k & 3) + ((k >> 2) & 1);
}
__device__ __forceinline__ float tf32r(float f) {
    uint32_t r;
    asm("cvt.rna.tf32.f32 %0, %1;" : "=r"(r) : "f"(f));
    return __uint_as_float(r);
}
__device__ __forceinline__ void mma8(float* c, uint32_t a0, uint32_t a1,
                                     uint32_t a2, uint32_t a3, uint32_t b0,
                                     uint32_t b1) {
    asm volatile(
        "mma.sync.aligned.m16n8k8.row.col.f32.tf32.tf32.f32 "
        "{%0,%1,%2,%3},{%4,%5,%6,%7},{%8,%9},{%0,%1,%2,%3};\n"
        : "+f"(c[0]), "+f"(c[1]), "+f"(c[2]), "+f"(c[3])
        : "r"(a0), "r"(a1), "r"(a2), "r"(a3), "r"(b0), "r"(b1));
}
__device__ __forceinline__ float tanh_fast(float x) {
    float t = __expf(2.0f * x);
    return 1.0f - __fdividef(2.0f, t + 1.0f);
}

__global__ void __launch_bounds__(NTHREADS, 1) sde_kernel(
    const float* __restrict__ x0, const float* __restrict__ noise,
    const float* __restrict__ Wd1, const float* __restrict__ bd1,
    const float* __restrict__ Wd2, const float* __restrict__ bd2,
    const float* __restrict__ Wg1, const float* __restrict__ bg1,
    const float* __restrict__ Wg2, const float* __restrict__ bg2,
    float* __restrict__ out) {
    extern __shared__ float sm[];
    const int tid = threadIdx.x;
    const int warp = tid >> 5, lane = tid & 31, g = lane >> 2, tg = lane & 3;
    const int group = warp >> 3;  // 0 = drift, 1 = diffusion
    const int wg = warp & 7;
    const int rowBase = blockIdx.x * ROWS;
    const int sw = 8 * (g & 3);

    // ── init: weights (tf32, transposed, perm+swz) ──────────────────
    for (int i = tid; i < DIMX * HIDX; i += NTHREADS) {
        int k = i >> 7, n = i & 127;  // W1[k][n]
        int p = permpos(k) ^ (8 * (n & 3));
        sm[OFF_W1D + n * 64 + p] = tf32r(Wd1[i]);
        sm[OFF_W1G + n * 64 + p] = tf32r(Wg1[i]);
        int k2 = i >> 6, n2 = i & 63;  // W2[k2][n2]
        int p2 = permpos(k2) ^ (8 * (n2 & 3));
        sm[OFF_W2D + n2 * 128 + p2] = tf32r(Wd2[i]);
        sm[OFF_W2G + n2 * 128 + p2] = tf32r(Wg2[i]);
    }
    for (int i = tid; i < HIDX; i += NTHREADS) {
        sm[OFF_B1D + i] = bd1[i];
        sm[OFF_B1G + i] = bg1[i];
    }
    for (int i = tid; i < DIMX; i += NTHREADS) {
        sm[OFF_B2D + i] = bd2[i];
        sm[OFF_B2G + i] = bg2[i];
    }
    // x0 -> smem (tf32 copy) + out[0]
    for (int i = tid; i < ROWS * DIMX; i += NTHREADS) {
        int r = i >> 6, c = i & 63;
        float v = x0[(rowBase + r) * DIMX + c];
        sm[OFF_X + r * 64 + (permpos(c) ^ (8 * (r & 3)))] = tf32r(v);
        out[(rowBase + r) * DIMX + c] = v;
    }

    // phase A tile (per group): 32x32, grid 2x4 over 64x128
    const int aR = 32 * (wg & 1), aC = 32 * (wg >> 1);
    // phase B tile (per group): 16x32, grid 4x2 over 64x64
    const int bR = 16 * (wg & 3), bC = 32 * (wg >> 2);

    // fp32 x state in registers (diffusion warps own all 64x64 elements)
    float2 xr[4][2];
    if (group == 1) {
#pragma unroll
        for (int n = 0; n < 4; n++)
#pragma unroll
            for (int h = 0; h < 2; h++) {
                int row = bR + 8 * h + g;
                int cc = bC + 8 * n + 2 * tg;
                xr[n][h] = *(const float2*)(x0 + (rowBase + row) * DIMX + cc);
            }
    }

    const float* w1 = sm + (group ? OFF_W1G : OFF_W1D);
    const float* b1s = sm + (group ? OFF_B1G : OFF_B1D);
    float* hbuf = sm + (group ? OFF_HG : OFF_HD);
    const float* w2 = sm + (group ? OFF_W2G : OFF_W2D);

    uint32_t smb;
    asm("{.reg .u64 t; cvta.to.shared.u64 t, %1; cvt.u32.u64 %0, t;}"
        : "=r"(smb) : "l"(sm));
    __syncthreads();

#pragma unroll 1
    for (int step = 0; step < NSTEPS; ++step) {
        // ── noise prefetch: drift group threads (0..255), cp.async ──
        if (group == 0) {
            const float* nzg = noise + ((size_t)step * BATCH + rowBase) * DIMX;
#pragma unroll
            for (int j = 0; j < 4; j++) {
                int chunk = j * 256 + tid;  // 1024 16B chunks
                int r = chunk >> 4, c4 = (chunk & 15) * 4;
                uint32_t dst = smb + (OFF_NZ + r * 64 + (c4 ^ (8 * (r & 3)))) * 4;
                asm volatile("cp.async.ca.shared.global [%0], [%1], 16;\n" ::
                                 "r"(dst), "l"(nzg + r * 64 + c4));
            }
            asm volatile("cp.async.commit_group;\n");
        }

        // ── phase A: h = tanh(x @ W1 + b1)  (32x32 tile per warp) ───
        {
            float ca[2][4][4] = {};
#pragma unroll
            for (int k8 = 0; k8 < 8; k8++) {
                const int ko = (k8 * 8 + 2 * tg) ^ sw;
                uint2 a[2][2];
#pragma unroll
                for (int m = 0; m < 2; m++) {
                    int r0 = aR + 16 * m + g;
                    a[m][0] = *(const uint2*)(sm + OFF_X + r0 * 64 + ko);
                    a[m][1] = *(const uint2*)(sm + OFF_X + (r0 + 8) * 64 + ko);
                }
#pragma unroll
                for (int n = 0; n < 4; n++) {
                    uint2 b_ = *(const uint2*)(w1 + (aC + 8 * n + g) * 64 + ko);
#pragma unroll
                    for (int m = 0; m < 2; m++)
                        mma8(ca[m][n], a[m][0].x, a[m][1].x, a[m][0].y,
                             a[m][1].y, b_.x, b_.y);
                }
            }
#pragma unroll
            for (int m = 0; m < 2; m++) {
                int r0 = aR + 16 * m + g;
#pragma unroll
                for (int n = 0; n < 4; n++) {
                    int cc = aC + 8 * n + 2 * tg;
                    int p0 = permpos(cc) ^ sw, p1 = permpos(cc + 1) ^ sw;
                    float d0 = b1s[cc], d1 = b1s[cc + 1];
                    hbuf[r0 * 128 + p0] = tf32r(tanh_fast(ca[m][n][0] + d0));
                    hbuf[r0 * 128 + p1] = tf32r(tanh_fast(ca[m][n][1] + d1));
                    hbuf[(r0 + 8) * 128 + p0] = tf32r(tanh_fast(ca[m][n][2] + d0));
                    hbuf[(r0 + 8) * 128 + p1] = tf32r(tanh_fast(ca[m][n][3] + d1));
                }
            }
        }
        __syncthreads();  // S1: h ready; diffusion done reading x

        // ── phase B: y = h @ W2  (16x32 tile per warp) ──────────────
        float cb[4][4] = {};
        {
#pragma unroll
            for (int k8 = 0; k8 < 16; k8++) {
                const int ko = (k8 * 8 + 2 * tg) ^ sw;
                uint2 a0 = *(const uint2*)(hbuf + (bR + g) * 128 + ko);
                uint2 a1 = *(const uint2*)(hbuf + (bR + 8 + g) * 128 + ko);
#pragma unroll
                for (int n = 0; n < 4; n++) {
                    uint2 b_ = *(const uint2*)(w2 + (bC + 8 * n + g) * 128 + ko);
                    mma8(cb[n], a0.x, a1.x, a0.y, a1.y, b_.x, b_.y);
                }
            }
        }
        if (group == 0) {
            // f (+bd2) -> X region (x tf32 copy is dead after S1)
#pragma unroll
            for (int n = 0; n < 4; n++) {
                int cc = bC + 8 * n + 2 * tg;
                int p0 = permpos(cc) ^ sw, p1 = permpos(cc + 1) ^ sw;
                float d0 = sm[OFF_B2D + cc], d1 = sm[OFF_B2D + cc + 1];
                sm[OFF_X + (bR + g) * 64 + p0] = cb[n][0] + d0;
                sm[OFF_X + (bR + g) * 64 + p1] = cb[n][1] + d1;
                sm[OFF_X + (bR + 8 + g) * 64 + p0] = cb[n][2] + d0;
                sm[OFF_X + (bR + 8 + g) * 64 + p1] = cb[n][3] + d1;
            }
            asm volatile("cp.async.wait_group 0;\n");
        }
        __syncthreads();  // S2: f + noise visible

        if (group == 1) {
            // combine: x += f*dt + (g+bg2)*dw*sqrt(dt); refresh smem x
            float* op = out + ((size_t)(step + 1) * BATCH + rowBase) * DIMX;
#pragma unroll
            for (int n = 0; n < 4; n++) {
                int cc = bC + 8 * n + 2 * tg;
                int p0 = permpos(cc) ^ sw, p1 = permpos(cc + 1) ^ sw;
                float e0 = sm[OFF_B2G + cc], e1 = sm[OFF_B2G + cc + 1];
#pragma unroll
                for (int h = 0; h < 2; h++) {
                    int row = bR + 8 * h + g;
                    float2 nz =
                        *(const float2*)(sm + OFF_NZ + row * 64 + (cc ^ sw));
                    float f0 = sm[OFF_X + row * 64 + p0];
                    float f1 = sm[OFF_X + row * 64 + p1];
                    float g0 = cb[n][2 * h + 0] + e0;
                    float g1 = cb[n][2 * h + 1] + e1;
                    float xn0 = xr[n][h].x + f0 * DT_C + g0 * (nz.x * SQDT_C);
                    float xn1 = xr[n][h].y + f1 * DT_C + g1 * (nz.y * SQDT_C);
                    xr[n][h] = make_float2(xn0, xn1);
                    sm[OFF_X + row * 64 + p0] = tf32r(xn0);
                    sm[OFF_X + row * 64 + p1] = tf32r(xn1);
                    *(float2*)(op + row * 64 + cc) = make_float2(xn0, xn1);
                }
            }
        }
        __syncthreads();  // S3: x ready for next step
    }
}

extern "C" void kernel_launch(void* const* d_in, const int* in_sizes, int n_in,
                              void* d_out, int out_size) {
    (void)in_sizes; (void)n_in; (void)out_size;
    const float* x0 = (const float*)d_in[0];
    // d_in[1] = t_span (unused)
    const float* noise = (const float*)d_in[2];
    const float* Wd1 = (const float*)d_in[3];
    const float* bd1 = (const float*)d_in[4];
    const float* Wd2 = (const float*)d_in[5];
    const float* bd2 = (const float*)d_in[6];
    const float* Wg1 = (const float*)d_in[7];
    const float* bg1 = (const float*)d_in[8];
    const float* Wg2 = (const float*)d_in[9];
    const float* bg2 = (const float*)d_in[10];
    float* out = (float*)d_out;

    cudaFuncSetAttribute(sde_kernel, cudaFuncAttributeMaxDynamicSharedMemorySize,
                         SMEM_BYTES);
    sde_kernel<<<NCTAS, NTHREADS, SMEM_BYTES>>>(x0, noise, Wd1, bd1, Wd2, bd2,
                                                Wg1, bg1, Wg2, bg2, out);
}